// round 15
// baseline (speedup 1.0000x reference)
#include <cuda_runtime.h>
#include <cuda_fp16.h>
#include <cstdint>

#define HWs  4096
#define DHW  262144

// ---------------- scratch (device globals; allocation-free rule) -----------
__device__ __half2 g_xth[(size_t)DHW * 8];    // x channel-last fp16 [v][c]
__device__ uint2   g_offh[(size_t)27 * DHW];  // offsets tap-major fp16 (oz,oy,ox,0)
__device__ uint4   g_BfragG[5184];            // gemm W frags [27][6][32] uint4
__device__ uint4   g_BfragD[864];             // einsum kern frags [27][32] uint4

// ---- helpers ----------------------------------------------------------------
__device__ __forceinline__ uint32_t smem_u32(const void* p) {
    uint32_t a;
    asm("{ .reg .u64 t; cvta.to.shared.u64 t, %1; cvt.u32.u64 %0, t; }" : "=r"(a) : "l"(p));
    return a;
}
__device__ __forceinline__ void cp_async16(uint32_t dst, const void* src) {
    asm volatile("cp.async.ca.shared.global [%0], [%1], 16;" :: "r"(dst), "l"(src) : "memory");
}
__device__ __forceinline__ void mma_f16(float* d, uint32_t a0, uint32_t a1,
                                        uint32_t a2, uint32_t a3,
                                        uint32_t b0, uint32_t b1) {
    asm volatile(
        "mma.sync.aligned.m16n8k16.row.col.f32.f16.f16.f32 "
        "{%0,%1,%2,%3}, {%4,%5,%6,%7}, {%8,%9}, {%0,%1,%2,%3};"
        : "+f"(d[0]), "+f"(d[1]), "+f"(d[2]), "+f"(d[3])
        : "r"(a0), "r"(a1), "r"(a2), "r"(a3), "r"(b0), "r"(b1));
}
#define LDM_X4(r, addr) asm volatile( \
    "ldmatrix.sync.aligned.m8n8.x4.shared.b16 {%0,%1,%2,%3}, [%4];" \
    : "=r"((r)[0]), "=r"((r)[1]), "=r"((r)[2]), "=r"((r)[3]) : "r"(addr))

// ---------------------------------------------------------------------------
// Prep A: gemm W fragments as uint4 = {nt=2np:(r0,r1), nt=2np+1:(r0,r1)}
// ---------------------------------------------------------------------------
__global__ void __launch_bounds__(256) k_bfragG(const float* __restrict__ pk)
{
    int idx = blockIdx.x * 256 + threadIdx.x;     // < 5184
    if (idx >= 5184) return;
    int tap = idx / 192;
    int rem = idx - tap * 192;
    int np  = rem >> 5;
    int l   = rem & 31;
    int c0  = 2 * (l & 3);
    int n0  = 16 * np + (l >> 2);
    int n1  = n0 + 8;
    int kb  = tap * 16;
    float a0 = (n0 < 81) ? pk[(kb + c0    ) * 81 + n0] : 0.f;
    float a1 = (n0 < 81) ? pk[(kb + c0 + 1) * 81 + n0] : 0.f;
    float b0 = (n0 < 81) ? pk[(kb + c0 + 8) * 81 + n0] : 0.f;
    float b1 = (n0 < 81) ? pk[(kb + c0 + 9) * 81 + n0] : 0.f;
    float c2 = (n1 < 81) ? pk[(kb + c0    ) * 81 + n1] : 0.f;
    float c3 = (n1 < 81) ? pk[(kb + c0 + 1) * 81 + n1] : 0.f;
    float d2 = (n1 < 81) ? pk[(kb + c0 + 8) * 81 + n1] : 0.f;
    float d3 = (n1 < 81) ? pk[(kb + c0 + 9) * 81 + n1] : 0.f;
    __half2 h0 = __floats2half2_rn(a0, a1);
    __half2 h1 = __floats2half2_rn(b0, b1);
    __half2 h2 = __floats2half2_rn(c2, c3);
    __half2 h3 = __floats2half2_rn(d2, d3);
    g_BfragG[idx] = make_uint4(*reinterpret_cast<uint32_t*>(&h0),
                               *reinterpret_cast<uint32_t*>(&h1),
                               *reinterpret_cast<uint32_t*>(&h2),
                               *reinterpret_cast<uint32_t*>(&h3));
}

// ---------------------------------------------------------------------------
// Prep B: einsum kern fragments as uint4 {nt0:(lo,hi), nt1:(lo,hi)}
// ---------------------------------------------------------------------------
__global__ void __launch_bounds__(256) k_bfragD(const float* __restrict__ kern)
{
    int idx = blockIdx.x * 256 + threadIdx.x;     // < 864
    if (idx >= 864) return;
    int tap = idx >> 5;
    int l   = idx & 31;
    int c0  = 2 * (l & 3);
    int o0  = l >> 2;
    int kb  = tap * 16;
    __half2 h0 = __floats2half2_rn(kern[(kb + c0    ) * 16 + o0],
                                   kern[(kb + c0 + 1) * 16 + o0]);
    __half2 h1 = __floats2half2_rn(kern[(kb + c0 + 8) * 16 + o0],
                                   kern[(kb + c0 + 9) * 16 + o0]);
    __half2 h2 = __floats2half2_rn(kern[(kb + c0    ) * 16 + o0 + 8],
                                   kern[(kb + c0 + 1) * 16 + o0 + 8]);
    __half2 h3 = __floats2half2_rn(kern[(kb + c0 + 8) * 16 + o0 + 8],
                                   kern[(kb + c0 + 9) * 16 + o0 + 8]);
    g_BfragD[idx] = make_uint4(*reinterpret_cast<uint32_t*>(&h0),
                               *reinterpret_cast<uint32_t*>(&h1),
                               *reinterpret_cast<uint32_t*>(&h2),
                               *reinterpret_cast<uint32_t*>(&h3));
}

// ---------------------------------------------------------------------------
// Kernel 0: transpose x [c][v] -> fp16 channel-last [v][c]
// ---------------------------------------------------------------------------
__global__ void __launch_bounds__(256) k_transpose(const float* __restrict__ x)
{
    int v = blockIdx.x * 256 + threadIdx.x;
    float vals[16];
#pragma unroll
    for (int c = 0; c < 16; c++)
        vals[c] = x[(size_t)c * DHW + v];
    __half2 h[8];
#pragma unroll
    for (int i = 0; i < 8; i++)
        h[i] = __floats2half2_rn(vals[2*i], vals[2*i+1]);
    uint4* dst = reinterpret_cast<uint4*>(g_xth + (size_t)v * 8);
    dst[0] = *reinterpret_cast<uint4*>(&h[0]);
    dst[1] = *reinterpret_cast<uint4*>(&h[4]);
}

// ---------------------------------------------------------------------------
// Kernel 1: offset GEMM (unchanged: cp.async double-buffered B).
// ---------------------------------------------------------------------------
__global__ void __launch_bounds__(256, 3) k_gemm()
{
    extern __shared__ char smem[];
    const uint32_t smem_base = smem_u32(smem);
    uint4* bsm = reinterpret_cast<uint4*>(smem);               // 2 x 576 uint4
    uint32_t* patch = reinterpret_cast<uint32_t*>(smem + 18432);
    float* stage = reinterpret_cast<float*>(smem);

    const int t    = threadIdx.x;
    const int lane = t & 31;
    const int w    = t >> 5;
    const int mg    = w >> 1;
    const int nhalf = w & 1;
    const int z    = blockIdx.y;
    const int y0   = blockIdx.x * 2;

#pragma unroll
    for (int g = 0; g < 2; g++) {
        for (int i = t; i < 576; i += 256)
            cp_async16(smem_base + (uint32_t)((g * 576 + i) * 16),
                       g_BfragG + g * 576 + i);
        asm volatile("cp.async.commit_group;" ::: "memory");
    }

    const uint4* xthq = reinterpret_cast<const uint4*>(g_xth);
    for (int j = t; j < 1584; j += 256) {
        int q    = j & 1;
        int slot = j >> 1;
        int px = slot % 66;
        int qq = slot / 66;
        int py = qq & 3, pz = qq >> 2;
        int gz = z - 1 + pz, gy = y0 - 1 + py, gx = px - 1;
        uint4 v = make_uint4(0u, 0u, 0u, 0u);
        if ((unsigned)gz < 64u && (unsigned)gy < 64u && (unsigned)gx < 64u)
            v = xthq[(size_t)(gz * HWs + gy * 64 + gx) * 2 + q];
        *reinterpret_cast<uint4*>(patch + slot * 12 + q * 4) = v;
    }

    const int rowInTile = (lane & 7) + ((lane >> 3) & 1) * 8;
    const int khalf = lane >> 4;
    uint32_t abase[2];
#pragma unroll
    for (int mt = 0; mt < 2; mt++) {
        int r  = mg * 32 + mt * 16 + rowInTile;
        int sy = r >> 6, sx = r & 63;
        abase[mt] = smem_base + 18432u + (uint32_t)((sy * 66 + sx) * 48) + khalf * 16u;
    }

    float d[48];
#pragma unroll
    for (int i = 0; i < 48; i++) d[i] = 0.f;

    uint32_t rowoff = 0;
    int gm = 0;
#pragma unroll 1
    for (int g = 0; g < 9; g++) {
        if (g < 8) { asm volatile("cp.async.wait_group 1;" ::: "memory"); }
        else       { asm volatile("cp.async.wait_group 0;" ::: "memory"); }
        __syncthreads();

        const uint4* bp = bsm + (g & 1) * 576 + nhalf * 96 + lane;
#pragma unroll
        for (int tl = 0; tl < 3; tl++) {
            const uint32_t aoff = rowoff + (uint32_t)(tl * 48);
            uint32_t A0[4], A1[4];
            LDM_X4(A0, abase[0] + aoff);
            LDM_X4(A1, abase[1] + aoff);
            const uint4* bpt = bp + tl * 192;
#pragma unroll
            for (int np = 0; np < 3; np++) {
                uint4 b = bpt[np * 32];
                float* d0 = d + (np * 4    ) * 4;
                float* d1 = d + (np * 4 + 1) * 4;
                float* d2 = d + (np * 4 + 2) * 4;
                float* d3 = d + (np * 4 + 3) * 4;
                mma_f16(d0, A0[0], A0[1], A0[2], A0[3], b.x, b.y);
                mma_f16(d1, A1[0], A1[1], A1[2], A1[3], b.x, b.y);
                mma_f16(d2, A0[0], A0[1], A0[2], A0[3], b.z, b.w);
                mma_f16(d3, A1[0], A1[1], A1[2], A1[3], b.z, b.w);
            }
        }
        __syncthreads();

        if (g + 2 < 9) {
            for (int i = t; i < 576; i += 256)
                cp_async16(smem_base + (uint32_t)(((g & 1) * 576 + i) * 16),
                           g_BfragG + (g + 2) * 576 + i);
        }
        asm volatile("cp.async.commit_group;" ::: "memory");

        rowoff += (uint32_t)(66 * 48);
        if (++gm == 3) { gm = 0; rowoff += (uint32_t)(66 * 48); }
    }
    asm volatile("cp.async.wait_group 0;" ::: "memory");
    __syncthreads();

    const int rlo  = lane >> 2;
    const int col0 = 2 * (lane & 3);
#pragma unroll
    for (int mt = 0; mt < 2; mt++) {
#pragma unroll
        for (int np = 0; np < 3; np++) {
#pragma unroll
            for (int ntl = 0; ntl < 2; ntl++) {
                const float* dd = d + ((np * 2 + ntl) * 2 + mt) * 4;
                int lr0 = mg * 32 + mt * 16 + rlo;
                int col = (2 * (nhalf * 3 + np) + ntl) * 8 + col0;
                stage[lr0 * 100 + col    ] = dd[0];
                stage[lr0 * 100 + col + 1] = dd[1];
                stage[(lr0 + 8) * 100 + col    ] = dd[2];
                stage[(lr0 + 8) * 100 + col + 1] = dd[3];
            }
        }
    }
    __syncthreads();

    for (int i = t; i < 3456; i += 256) {
        int tap = i >> 7;
        int v   = i & 127;
        int vox = z * HWs + (y0 + (v >> 6)) * 64 + (v & 63);
        const float* s = stage + v * 100 + 3 * tap;
        __half2 h0 = __floats2half2_rn(s[0], s[1]);
        __half2 h1 = __floats2half2_rn(s[2], 0.f);
        g_offh[(size_t)tap * DHW + vox] =
            make_uint2(*reinterpret_cast<uint32_t*>(&h0),
                       *reinterpret_cast<uint32_t*>(&h1));
    }
}

// ---------------------------------------------------------------------------
// Kernel 2: deformable gather + HMMA einsum. 256 thr / 8 warps, 4x8x8 tile,
// 3 blocks/SM. A-stage double-buffered (1 syncwarp/tap); offset + kern-frag
// loads software-pipelined one tap ahead; kern frags read direct from gmem.
// SMEM: region 2 planes x [9][13][13] x 16 B @0 (48672 B);
//       A stage 8 warps x 2048 B @48672. Total 65056 B.
// ---------------------------------------------------------------------------
__global__ void __launch_bounds__(256, 3) k_deform(float* __restrict__ out)
{
    extern __shared__ char smem[];
    const uint4* xrq = reinterpret_cast<const uint4*>(smem);   // 2 x 1521 uint4
    const uint32_t smem_base = smem_u32(smem);

    const int t    = threadIdx.x;
    const int lane = t & 31;
    const int w    = t >> 5;

    const int bz = blockIdx.z * 4, by = blockIdx.y * 8, bx = blockIdx.x * 8;
    const int roz = bz - 2, roy = by - 2, rox = bx - 2;

    // region: 1521 points x 2 planes (ch0-7, ch8-15), 16 B each
    {
        const uint4* xthq = reinterpret_cast<const uint4*>(g_xth);
        uint4* xw = reinterpret_cast<uint4*>(smem);
        for (int u = t; u < 3042; u += 256) {
            int q = u & 1;
            int p = u >> 1;
            int rx = p % 13;
            int p2 = p / 13;
            int ry = p2 % 13;
            int rz = p2 / 13;
            int gz = roz + rz, gy = roy + ry, gx = rox + rx;
            uint4 v = make_uint4(0u, 0u, 0u, 0u);
            if ((unsigned)gz < 64u && (unsigned)gy < 64u && (unsigned)gx < 64u)
                v = xthq[(size_t)(gz * HWs + gy * 64 + gx) * 2 + q];
            xw[q * 1521 + p] = v;
        }
    }
    __syncthreads();

    const int lx = t & 7, ly = (t >> 3) & 7, lz = t >> 6;   // lz 0..3
    const int pz = bz + lz, py = by + ly, px = bx + lx;
    const int vox = pz * HWs + py * 64 + px;
    const uint2* offp = g_offh + vox;

    // A-stage: per-warp 2 x 1024 B, layout [buf][mt][khalf][row*16]
    const uint32_t asb = 48672u + (uint32_t)w * 2048u;
    const uint32_t stoff = asb + ((uint32_t)(lane >> 4)) * 512u
                         + (uint32_t)(lane & 15) * 16u;
    const uint32_t adr0  = smem_base + asb + (uint32_t)(lane & 15) * 16u
                         + (uint32_t)(lane >> 4) * 256u;

    float d[16];
#pragma unroll
    for (int q = 0; q < 16; q++) d[q] = 0.f;

    const uint4* bgl = g_BfragD + lane;
    uint2 ob = offp[0];          // prefetched offset (tap 0)
    uint4 bb = bgl[0];           // prefetched kern frag (tap 0)

    int kd = 0, kh = 0, kw = 0;
#pragma unroll 1
    for (int k = 0; k < 27; k++) {
        // prefetch next tap's offset + kern frag
        uint2 obn = ob;
        uint4 bbn = bb;
        if (k < 26) {
            obn = offp[(size_t)(k + 1) * DHW];
            bbn = bgl[(k + 1) * 32];
        }

        float2 ozy = __half22float2(*reinterpret_cast<__half2*>(&ob.x));
        float2 oxp = __half22float2(*reinterpret_cast<__half2*>(&ob.y));
        float cz = (float)(pz + kd - 1) + ozy.x;
        float cy = (float)(py + kh - 1) + ozy.y;
        float cx = (float)(px + kw - 1) + oxp.x;
        if (++kw == 3) { kw = 0; if (++kh == 3) { kh = 0; ++kd; } }

        float z0f = floorf(cz), y0f = floorf(cy), x0f = floorf(cx);
        float fz = cz - z0f, fy = cy - y0f, fx = cx - x0f;
        int z0 = (int)z0f, y0 = (int)y0f, x0 = (int)x0f;
        int lz0 = z0 - roz, ly0 = y0 - roy, lx0 = x0 - rox;

        const __half2 wx0h = __float2half2_rn(1.f - fx);
        const __half2 wx1h = __float2half2_rn(fx);

        __half2 ah[8];
#pragma unroll
        for (int j = 0; j < 8; j++) ah[j] = __float2half2_rn(0.f);

        if ((unsigned)lz0 <= 7u && (unsigned)ly0 <= 11u && (unsigned)lx0 <= 11u) {
            // fast path: batch one z-slab's 8 loads, then consume (MLP 8)
#pragma unroll
            for (int dz = 0; dz < 2; dz++) {
                float wz = dz ? fz : 1.f - fz;
                const int ptb = (lz0 + dz) * 169 + ly0 * 13 + lx0;
                uint4 p0a = xrq[ptb];             uint4 q0a = xrq[ptb + 1];
                uint4 p1a = xrq[1521 + ptb];      uint4 q1a = xrq[1521 + ptb + 1];
                uint4 p0b = xrq[ptb + 13];        uint4 q0b = xrq[ptb + 14];
                uint4 p1b = xrq[1521 + ptb + 13]; uint4 q1b = xrq[1521 + ptb + 14];
                __half2 wa = __float2half2_rn(wz * (1.f - fy));
                __half2 wb = __float2half2_rn(wz * fy);
#pragma unroll
                for (int j = 0; j < 4; j++) {
                    __half2 ta = __hfma2(*(reinterpret_cast<__half2*>(&q0a) + j), wx1h,
                                 __hmul2(*(reinterpret_cast<__half2*>(&p0a) + j), wx0h));
                    ah[j] = __hfma2(ta, wa, ah[j]);
                    __half2 ua = __hfma2(*(reinterpret_cast<__half2*>(&q1a) + j), wx1h,
                                 __hmul2(*(reinterpret_cast<__half2*>(&p1a) + j), wx0h));
                    ah[j + 4] = __hfma2(ua, wa, ah[j + 4]);
                    __half2 tb = __hfma2(*(reinterpret_cast<__half2*>(&q0b) + j), wx1h,
                                 __hmul2(*(reinterpret_cast<__half2*>(&p0b) + j), wx0h));
                    ah[j] = __hfma2(tb, wb, ah[j]);
                    __half2 ub = __hfma2(*(reinterpret_cast<__half2*>(&q1b) + j), wx1h,
                                 __hmul2(*(reinterpret_cast<__half2*>(&p1b) + j), wx0h));
                    ah[j + 4] = __hfma2(ub, wb, ah[j + 4]);
                }
            }
        } else {
            // exact fallback: per-corner validity, global fp16 reads
#pragma unroll
            for (int dz = 0; dz < 2; dz++) {
                float wz = dz ? fz : 1.f - fz;
#pragma unroll
                for (int dy = 0; dy < 2; dy++) {
                    __half2 wzyh = __float2half2_rn(wz * (dy ? fy : 1.f - fy));
                    int zi = z0 + dz, yi = y0 + dy;
                    bool okzy = ((unsigned)zi < 64u) && ((unsigned)yi < 64u);
                    uint4 p0 = make_uint4(0,0,0,0), p1 = p0, q0 = p0, q1 = p0;
                    if (okzy && (unsigned)x0 < 64u) {
                        const uint4* g = reinterpret_cast<const uint4*>(
                            g_xth + (size_t)(zi * HWs + yi * 64 + x0) * 8);
                        p0 = g[0]; p1 = g[1];
                    }
                    if (okzy && (unsigned)(x0 + 1) < 64u) {
                        const uint4* g = reinterpret_cast<const uint4*>(
                            g_xth + (size_t)(zi * HWs + yi * 64 + x0 + 1) * 8);
                        q0 = g[0]; q1 = g[1];
                    }
#pragma unroll
                    for (int j = 0; j < 4; j++) {
                        __half2 pj = *(reinterpret_cast<__half2*>(&p0) + j);
                        __half2 qj = *(reinterpret_cast<__half2*>(&q0) + j);
                        __half2 tj = __hfma2(qj, wx1h, __hmul2(pj, wx0h));
                        ah[j] = __hfma2(tj, wzyh, ah[j]);
                        __half2 pk2 = *(reinterpret_cast<__half2*>(&p1) + j);
                        __half2 qk2 = *(reinterpret_cast<__half2*>(&q1) + j);
                        __half2 uk = __hfma2(qk2, wx1h, __hmul2(pk2, wx0h));
                        ah[j + 4] = __hfma2(uk, wzyh, ah[j + 4]);
                    }
                }
            }
        }

        // ---- einsum via HMMA: stage ah (double-buffered) -> ldmatrix -> mma
        const uint32_t bufo = (uint32_t)(k & 1) * 1024u;
        uint4* s0 = reinterpret_cast<uint4*>(smem + stoff + bufo);
        s0[0]  = *reinterpret_cast<uint4*>(&ah[0]);
        s0[16] = *reinterpret_cast<uint4*>(&ah[4]);   // khalf1 @ +256 B
        __syncwarp();                                 // RAW only (buffers alternate)
        uint32_t A0[4], A1[4];
        LDM_X4(A0, adr0 + bufo);
        LDM_X4(A1, adr0 + bufo + 512u);
        mma_f16(d,      A0[0], A0[1], A0[2], A0[3], bb.x, bb.y);
        mma_f16(d + 8,  A1[0], A1[1], A1[2], A1[3], bb.x, bb.y);
        mma_f16(d + 4,  A0[0], A0[1], A0[2], A0[3], bb.z, bb.w);
        mma_f16(d + 12, A1[0], A1[1], A1[2], A1[3], bb.z, bb.w);

        ob = obn;
        bb = bbn;
    }

    // ---- write out ----
    const int rlo = lane >> 2;
    const int o0  = 2 * (lane & 3);
#pragma unroll
    for (int mt = 0; mt < 2; mt++) {
#pragma unroll
        for (int nt = 0; nt < 2; nt++) {
            const float* dd = d + mt * 8 + nt * 4;
            int vlo = mt * 16 + rlo;
            int vhi = vlo + 8;
            int vox_lo = (bz + (w >> 1)) * HWs
                       + (by + (w & 1) * 4 + (vlo >> 3)) * 64 + bx + (vlo & 7);
            int vox_hi = (bz + (w >> 1)) * HWs
                       + (by + (w & 1) * 4 + (vhi >> 3)) * 64 + bx + (vhi & 7);
            out[(size_t)(nt * 8 + o0    ) * DHW + vox_lo] = dd[0];
            out[(size_t)(nt * 8 + o0 + 1) * DHW + vox_lo] = dd[1];
            out[(size_t)(nt * 8 + o0    ) * DHW + vox_hi] = dd[2];
            out[(size_t)(nt * 8 + o0 + 1) * DHW + vox_hi] = dd[3];
        }
    }
}

// ---------------------------------------------------------------------------
extern "C" void kernel_launch(void* const* d_in, const int* in_sizes, int n_in,
                              void* d_out, int out_size)
{
    const float* x    = (const float*)d_in[0];   // [16,64,64,64]
    const float* kern = (const float*)d_in[1];   // [27,16,16]
    const float* pk   = (const float*)d_in[2];   // [27,16,81]
    float* out = (float*)d_out;                  // [16,64,64,64]

    cudaFuncSetAttribute(k_gemm,   cudaFuncAttributeMaxDynamicSharedMemorySize, 56448);
    cudaFuncSetAttribute(k_deform, cudaFuncAttributeMaxDynamicSharedMemorySize, 65056);

    k_bfragG<<<21, 256>>>(pk);
    k_bfragD<<<4, 256>>>(kern);
    k_transpose<<<1024, 256>>>(x);
    k_gemm<<<dim3(32, 64), 256, 56448>>>();
    k_deform<<<dim3(8, 8, 16), 256, 65056>>>(out);
}

// round 16
// speedup vs baseline: 1.0605x; 1.0605x over previous
#include <cuda_runtime.h>
#include <cuda_fp16.h>
#include <cstdint>

#define HWs  4096
#define DHW  262144

// ---------------- scratch (device globals; allocation-free rule) -----------
__device__ __half2 g_xth[(size_t)DHW * 8];    // x channel-last fp16 [v][c]
__device__ uint2   g_offh[(size_t)27 * DHW];  // offsets tap-major fp16 (oz,oy,ox,0)
__device__ uint4   g_BfragG[5184];            // gemm W frags [27][6][32] uint4
__device__ uint4   g_BfragD[864];             // einsum kern frags [27][32] uint4

// ---- helpers ----------------------------------------------------------------
__device__ __forceinline__ uint32_t smem_u32(const void* p) {
    uint32_t a;
    asm("{ .reg .u64 t; cvta.to.shared.u64 t, %1; cvt.u32.u64 %0, t; }" : "=r"(a) : "l"(p));
    return a;
}
__device__ __forceinline__ void cp_async16(uint32_t dst, const void* src) {
    asm volatile("cp.async.ca.shared.global [%0], [%1], 16;" :: "r"(dst), "l"(src) : "memory");
}
__device__ __forceinline__ void mma_f16(float* d, uint32_t a0, uint32_t a1,
                                        uint32_t a2, uint32_t a3,
                                        uint32_t b0, uint32_t b1) {
    asm volatile(
        "mma.sync.aligned.m16n8k16.row.col.f32.f16.f16.f32 "
        "{%0,%1,%2,%3}, {%4,%5,%6,%7}, {%8,%9}, {%0,%1,%2,%3};"
        : "+f"(d[0]), "+f"(d[1]), "+f"(d[2]), "+f"(d[3])
        : "r"(a0), "r"(a1), "r"(a2), "r"(a3), "r"(b0), "r"(b1));
}
#define LDM_X4(r, addr) asm volatile( \
    "ldmatrix.sync.aligned.m8n8.x4.shared.b16 {%0,%1,%2,%3}, [%4];" \
    : "=r"((r)[0]), "=r"((r)[1]), "=r"((r)[2]), "=r"((r)[3]) : "r"(addr))

// ---------------------------------------------------------------------------
// Kernel P: merged prep — blocks 0..1023 transpose x -> fp16 channel-last;
// blocks 1024..1044 build gemm W frags; blocks 1045..1048 build kern frags.
// ---------------------------------------------------------------------------
__global__ void __launch_bounds__(256) k_prep(const float* __restrict__ x,
                                              const float* __restrict__ pk,
                                              const float* __restrict__ kern)
{
    const int b = blockIdx.x;
    const int t = threadIdx.x;

    if (b < 1024) {
        // ---- transpose ----
        int v = b * 256 + t;
        float vals[16];
#pragma unroll
        for (int c = 0; c < 16; c++)
            vals[c] = x[(size_t)c * DHW + v];
        __half2 h[8];
#pragma unroll
        for (int i = 0; i < 8; i++)
            h[i] = __floats2half2_rn(vals[2*i], vals[2*i+1]);
        uint4* dst = reinterpret_cast<uint4*>(g_xth + (size_t)v * 8);
        dst[0] = *reinterpret_cast<uint4*>(&h[0]);
        dst[1] = *reinterpret_cast<uint4*>(&h[4]);
    } else if (b < 1045) {
        // ---- gemm W fragments ----
        int idx = (b - 1024) * 256 + t;
        if (idx >= 5184) return;
        int tap = idx / 192;
        int rem = idx - tap * 192;
        int np  = rem >> 5;
        int l   = rem & 31;
        int c0  = 2 * (l & 3);
        int n0  = 16 * np + (l >> 2);
        int n1  = n0 + 8;
        int kb  = tap * 16;
        float a0 = (n0 < 81) ? pk[(kb + c0    ) * 81 + n0] : 0.f;
        float a1 = (n0 < 81) ? pk[(kb + c0 + 1) * 81 + n0] : 0.f;
        float b0 = (n0 < 81) ? pk[(kb + c0 + 8) * 81 + n0] : 0.f;
        float b1 = (n0 < 81) ? pk[(kb + c0 + 9) * 81 + n0] : 0.f;
        float c2 = (n1 < 81) ? pk[(kb + c0    ) * 81 + n1] : 0.f;
        float c3 = (n1 < 81) ? pk[(kb + c0 + 1) * 81 + n1] : 0.f;
        float d2 = (n1 < 81) ? pk[(kb + c0 + 8) * 81 + n1] : 0.f;
        float d3 = (n1 < 81) ? pk[(kb + c0 + 9) * 81 + n1] : 0.f;
        __half2 h0 = __floats2half2_rn(a0, a1);
        __half2 h1 = __floats2half2_rn(b0, b1);
        __half2 h2 = __floats2half2_rn(c2, c3);
        __half2 h3 = __floats2half2_rn(d2, d3);
        g_BfragG[idx] = make_uint4(*reinterpret_cast<uint32_t*>(&h0),
                                   *reinterpret_cast<uint32_t*>(&h1),
                                   *reinterpret_cast<uint32_t*>(&h2),
                                   *reinterpret_cast<uint32_t*>(&h3));
    } else {
        // ---- einsum kern fragments ----
        int idx = (b - 1045) * 256 + t;
        if (idx >= 864) return;
        int tap = idx >> 5;
        int l   = idx & 31;
        int c0  = 2 * (l & 3);
        int o0  = l >> 2;
        int kb  = tap * 16;
        __half2 h0 = __floats2half2_rn(kern[(kb + c0    ) * 16 + o0],
                                       kern[(kb + c0 + 1) * 16 + o0]);
        __half2 h1 = __floats2half2_rn(kern[(kb + c0 + 8) * 16 + o0],
                                       kern[(kb + c0 + 9) * 16 + o0]);
        __half2 h2 = __floats2half2_rn(kern[(kb + c0    ) * 16 + o0 + 8],
                                       kern[(kb + c0 + 1) * 16 + o0 + 8]);
        __half2 h3 = __floats2half2_rn(kern[(kb + c0 + 8) * 16 + o0 + 8],
                                       kern[(kb + c0 + 9) * 16 + o0 + 8]);
        g_BfragD[idx] = make_uint4(*reinterpret_cast<uint32_t*>(&h0),
                                   *reinterpret_cast<uint32_t*>(&h1),
                                   *reinterpret_cast<uint32_t*>(&h2),
                                   *reinterpret_cast<uint32_t*>(&h3));
    }
}

// ---------------------------------------------------------------------------
// Kernel 1: offset GEMM (unchanged: cp.async double-buffered B).
// ---------------------------------------------------------------------------
__global__ void __launch_bounds__(256, 3) k_gemm()
{
    extern __shared__ char smem[];
    const uint32_t smem_base = smem_u32(smem);
    uint4* bsm = reinterpret_cast<uint4*>(smem);               // 2 x 576 uint4
    uint32_t* patch = reinterpret_cast<uint32_t*>(smem + 18432);
    float* stage = reinterpret_cast<float*>(smem);

    const int t    = threadIdx.x;
    const int lane = t & 31;
    const int w    = t >> 5;
    const int mg    = w >> 1;
    const int nhalf = w & 1;
    const int z    = blockIdx.y;
    const int y0   = blockIdx.x * 2;

#pragma unroll
    for (int g = 0; g < 2; g++) {
        for (int i = t; i < 576; i += 256)
            cp_async16(smem_base + (uint32_t)((g * 576 + i) * 16),
                       g_BfragG + g * 576 + i);
        asm volatile("cp.async.commit_group;" ::: "memory");
    }

    const uint4* xthq = reinterpret_cast<const uint4*>(g_xth);
    for (int j = t; j < 1584; j += 256) {
        int q    = j & 1;
        int slot = j >> 1;
        int px = slot % 66;
        int qq = slot / 66;
        int py = qq & 3, pz = qq >> 2;
        int gz = z - 1 + pz, gy = y0 - 1 + py, gx = px - 1;
        uint4 v = make_uint4(0u, 0u, 0u, 0u);
        if ((unsigned)gz < 64u && (unsigned)gy < 64u && (unsigned)gx < 64u)
            v = xthq[(size_t)(gz * HWs + gy * 64 + gx) * 2 + q];
        *reinterpret_cast<uint4*>(patch + slot * 12 + q * 4) = v;
    }

    const int rowInTile = (lane & 7) + ((lane >> 3) & 1) * 8;
    const int khalf = lane >> 4;
    uint32_t abase[2];
#pragma unroll
    for (int mt = 0; mt < 2; mt++) {
        int r  = mg * 32 + mt * 16 + rowInTile;
        int sy = r >> 6, sx = r & 63;
        abase[mt] = smem_base + 18432u + (uint32_t)((sy * 66 + sx) * 48) + khalf * 16u;
    }

    float d[48];
#pragma unroll
    for (int i = 0; i < 48; i++) d[i] = 0.f;

    uint32_t rowoff = 0;
    int gm = 0;
#pragma unroll 1
    for (int g = 0; g < 9; g++) {
        if (g < 8) { asm volatile("cp.async.wait_group 1;" ::: "memory"); }
        else       { asm volatile("cp.async.wait_group 0;" ::: "memory"); }
        __syncthreads();

        const uint4* bp = bsm + (g & 1) * 576 + nhalf * 96 + lane;
#pragma unroll
        for (int tl = 0; tl < 3; tl++) {
            const uint32_t aoff = rowoff + (uint32_t)(tl * 48);
            uint32_t A0[4], A1[4];
            LDM_X4(A0, abase[0] + aoff);
            LDM_X4(A1, abase[1] + aoff);
            const uint4* bpt = bp + tl * 192;
#pragma unroll
            for (int np = 0; np < 3; np++) {
                uint4 b = bpt[np * 32];
                float* d0 = d + (np * 4    ) * 4;
                float* d1 = d + (np * 4 + 1) * 4;
                float* d2 = d + (np * 4 + 2) * 4;
                float* d3 = d + (np * 4 + 3) * 4;
                mma_f16(d0, A0[0], A0[1], A0[2], A0[3], b.x, b.y);
                mma_f16(d1, A1[0], A1[1], A1[2], A1[3], b.x, b.y);
                mma_f16(d2, A0[0], A0[1], A0[2], A0[3], b.z, b.w);
                mma_f16(d3, A1[0], A1[1], A1[2], A1[3], b.z, b.w);
            }
        }
        __syncthreads();

        if (g + 2 < 9) {
            for (int i = t; i < 576; i += 256)
                cp_async16(smem_base + (uint32_t)(((g & 1) * 576 + i) * 16),
                           g_BfragG + (g + 2) * 576 + i);
        }
        asm volatile("cp.async.commit_group;" ::: "memory");

        rowoff += (uint32_t)(66 * 48);
        if (++gm == 3) { gm = 0; rowoff += (uint32_t)(66 * 48); }
    }
    asm volatile("cp.async.wait_group 0;" ::: "memory");
    __syncthreads();

    const int rlo  = lane >> 2;
    const int col0 = 2 * (lane & 3);
#pragma unroll
    for (int mt = 0; mt < 2; mt++) {
#pragma unroll
        for (int np = 0; np < 3; np++) {
#pragma unroll
            for (int ntl = 0; ntl < 2; ntl++) {
                const float* dd = d + ((np * 2 + ntl) * 2 + mt) * 4;
                int lr0 = mg * 32 + mt * 16 + rlo;
                int col = (2 * (nhalf * 3 + np) + ntl) * 8 + col0;
                stage[lr0 * 100 + col    ] = dd[0];
                stage[lr0 * 100 + col + 1] = dd[1];
                stage[(lr0 + 8) * 100 + col    ] = dd[2];
                stage[(lr0 + 8) * 100 + col + 1] = dd[3];
            }
        }
    }
    __syncthreads();

    for (int i = t; i < 3456; i += 256) {
        int tap = i >> 7;
        int v   = i & 127;
        int vox = z * HWs + (y0 + (v >> 6)) * 64 + (v & 63);
        const float* s = stage + v * 100 + 3 * tap;
        __half2 h0 = __floats2half2_rn(s[0], s[1]);
        __half2 h1 = __floats2half2_rn(s[2], 0.f);
        g_offh[(size_t)tap * DHW + vox] =
            make_uint2(*reinterpret_cast<uint32_t*>(&h0),
                       *reinterpret_cast<uint32_t*>(&h1));
    }
}

// ---------------------------------------------------------------------------
// Kernel 2: deformable gather + HMMA einsum (exact R14 configuration).
// 256 thr / 8 warps, 4x8x8 tile, 3 blocks/SM. Fast path batches a z-slab's
// 8 region loads before consuming (MLP 8).
// SMEM: region 2 planes x [9][13][13] x 16 B @0 (48672 B);
//       kern frags 13824 B @48672; A stage 8 x 1024 B @62496 = 70688 B.
// ---------------------------------------------------------------------------
__global__ void __launch_bounds__(256, 3) k_deform(float* __restrict__ out)
{
    extern __shared__ char smem[];
    const uint4* xrq = reinterpret_cast<const uint4*>(smem);   // 2 x 1521 uint4
    const uint4* bfr = reinterpret_cast<const uint4*>(smem + 48672);
    const uint32_t smem_base = smem_u32(smem);

    const int t    = threadIdx.x;
    const int lane = t & 31;
    const int w    = t >> 5;

    {
        uint4* bd = reinterpret_cast<uint4*>(smem + 48672);
        for (int i = t; i < 864; i += 256) bd[i] = g_BfragD[i];
    }

    const int bz = blockIdx.z * 4, by = blockIdx.y * 8, bx = blockIdx.x * 8;
    const int roz = bz - 2, roy = by - 2, rox = bx - 2;

    // region: 1521 points x 2 planes (ch0-7, ch8-15), 16 B each
    {
        const uint4* xthq = reinterpret_cast<const uint4*>(g_xth);
        uint4* xw = reinterpret_cast<uint4*>(smem);
        for (int u = t; u < 3042; u += 256) {
            int q = u & 1;
            int p = u >> 1;
            int rx = p % 13;
            int p2 = p / 13;
            int ry = p2 % 13;
            int rz = p2 / 13;
            int gz = roz + rz, gy = roy + ry, gx = rox + rx;
            uint4 v = make_uint4(0u, 0u, 0u, 0u);
            if ((unsigned)gz < 64u && (unsigned)gy < 64u && (unsigned)gx < 64u)
                v = xthq[(size_t)(gz * HWs + gy * 64 + gx) * 2 + q];
            xw[q * 1521 + p] = v;
        }
    }
    __syncthreads();

    const int lx = t & 7, ly = (t >> 3) & 7, lz = t >> 6;   // lz 0..3
    const int pz = bz + lz, py = by + ly, px = bx + lx;
    const int vox = pz * HWs + py * 64 + px;
    const uint2* offp = g_offh + vox;

    // A-stage: per-warp 1024 B, layout [mt(lane>>4)][khalf][row(lane&15)*16]
    const uint32_t asb = 62496u + (uint32_t)w * 1024u;
    const uint32_t rowbase = asb + ((uint32_t)(lane >> 4)) * 512u
                           + (uint32_t)(lane & 15) * 16u;
    uint4* st0 = reinterpret_cast<uint4*>(smem + rowbase);
    uint4* st1 = reinterpret_cast<uint4*>(smem + rowbase + 256);
    const uint32_t addrA0 = smem_base + asb + (uint32_t)(lane & 15) * 16u
                          + (uint32_t)(lane >> 4) * 256u;
    const uint32_t addrA1 = addrA0 + 512u;

    float d[16];
#pragma unroll
    for (int q = 0; q < 16; q++) d[q] = 0.f;

    int kd = 0, kh = 0, kw = 0;
#pragma unroll 1
    for (int k = 0; k < 27; k++) {
        uint2 ob = offp[(size_t)k * DHW];
        float2 ozy = __half22float2(*reinterpret_cast<__half2*>(&ob.x));
        float2 oxp = __half22float2(*reinterpret_cast<__half2*>(&ob.y));
        float cz = (float)(pz + kd - 1) + ozy.x;
        float cy = (float)(py + kh - 1) + ozy.y;
        float cx = (float)(px + kw - 1) + oxp.x;
        if (++kw == 3) { kw = 0; if (++kh == 3) { kh = 0; ++kd; } }

        float z0f = floorf(cz), y0f = floorf(cy), x0f = floorf(cx);
        float fz = cz - z0f, fy = cy - y0f, fx = cx - x0f;
        int z0 = (int)z0f, y0 = (int)y0f, x0 = (int)x0f;
        int lz0 = z0 - roz, ly0 = y0 - roy, lx0 = x0 - rox;

        const __half2 wx0h = __float2half2_rn(1.f - fx);
        const __half2 wx1h = __float2half2_rn(fx);

        __half2 ah[8];
#pragma unroll
        for (int j = 0; j < 8; j++) ah[j] = __float2half2_rn(0.f);

        if ((unsigned)lz0 <= 7u && (unsigned)ly0 <= 11u && (unsigned)lx0 <= 11u) {
            // fast path: batch one z-slab's 8 loads, then consume (MLP 8)
#pragma unroll
            for (int dz = 0; dz < 2; dz++) {
                float wz = dz ? fz : 1.f - fz;
                const int ptb = (lz0 + dz) * 169 + ly0 * 13 + lx0;
                uint4 p0a = xrq[ptb];             uint4 q0a = xrq[ptb + 1];
                uint4 p1a = xrq[1521 + ptb];      uint4 q1a = xrq[1521 + ptb + 1];
                uint4 p0b = xrq[ptb + 13];        uint4 q0b = xrq[ptb + 14];
                uint4 p1b = xrq[1521 + ptb + 13]; uint4 q1b = xrq[1521 + ptb + 14];
                __half2 wa = __float2half2_rn(wz * (1.f - fy));
                __half2 wb = __float2half2_rn(wz * fy);
#pragma unroll
                for (int j = 0; j < 4; j++) {
                    __half2 ta = __hfma2(*(reinterpret_cast<__half2*>(&q0a) + j), wx1h,
                                 __hmul2(*(reinterpret_cast<__half2*>(&p0a) + j), wx0h));
                    ah[j] = __hfma2(ta, wa, ah[j]);
                    __half2 ua = __hfma2(*(reinterpret_cast<__half2*>(&q1a) + j), wx1h,
                                 __hmul2(*(reinterpret_cast<__half2*>(&p1a) + j), wx0h));
                    ah[j + 4] = __hfma2(ua, wa, ah[j + 4]);
                    __half2 tb = __hfma2(*(reinterpret_cast<__half2*>(&q0b) + j), wx1h,
                                 __hmul2(*(reinterpret_cast<__half2*>(&p0b) + j), wx0h));
                    ah[j] = __hfma2(tb, wb, ah[j]);
                    __half2 ub = __hfma2(*(reinterpret_cast<__half2*>(&q1b) + j), wx1h,
                                 __hmul2(*(reinterpret_cast<__half2*>(&p1b) + j), wx0h));
                    ah[j + 4] = __hfma2(ub, wb, ah[j + 4]);
                }
            }
        } else {
            // exact fallback: per-corner validity, global fp16 reads
#pragma unroll
            for (int dz = 0; dz < 2; dz++) {
                float wz = dz ? fz : 1.f - fz;
#pragma unroll
                for (int dy = 0; dy < 2; dy++) {
                    __half2 wzyh = __float2half2_rn(wz * (dy ? fy : 1.f - fy));
                    int zi = z0 + dz, yi = y0 + dy;
                    bool okzy = ((unsigned)zi < 64u) && ((unsigned)yi < 64u);
                    uint4 p0 = make_uint4(0,0,0,0), p1 = p0, q0 = p0, q1 = p0;
                    if (okzy && (unsigned)x0 < 64u) {
                        const uint4* g = reinterpret_cast<const uint4*>(
                            g_xth + (size_t)(zi * HWs + yi * 64 + x0) * 8);
                        p0 = g[0]; p1 = g[1];
                    }
                    if (okzy && (unsigned)(x0 + 1) < 64u) {
                        const uint4* g = reinterpret_cast<const uint4*>(
                            g_xth + (size_t)(zi * HWs + yi * 64 + x0 + 1) * 8);
                        q0 = g[0]; q1 = g[1];
                    }
#pragma unroll
                    for (int j = 0; j < 4; j++) {
                        __half2 pj = *(reinterpret_cast<__half2*>(&p0) + j);
                        __half2 qj = *(reinterpret_cast<__half2*>(&q0) + j);
                        __half2 tj = __hfma2(qj, wx1h, __hmul2(pj, wx0h));
                        ah[j] = __hfma2(tj, wzyh, ah[j]);
                        __half2 pk2 = *(reinterpret_cast<__half2*>(&p1) + j);
                        __half2 qk2 = *(reinterpret_cast<__half2*>(&q1) + j);
                        __half2 uk = __hfma2(qk2, wx1h, __hmul2(pk2, wx0h));
                        ah[j + 4] = __hfma2(uk, wzyh, ah[j + 4]);
                    }
                }
            }
        }

        // ---- einsum via HMMA: stage ah -> ldmatrix -> mma ----
        __syncwarp();
        st0[0] = *reinterpret_cast<uint4*>(&ah[0]);
        st1[0] = *reinterpret_cast<uint4*>(&ah[4]);
        __syncwarp();
        uint32_t A0[4], A1[4];
        LDM_X4(A0, addrA0);
        LDM_X4(A1, addrA1);
        uint4 b = bfr[k * 32 + lane];
        mma_f16(d,      A0[0], A0[1], A0[2], A0[3], b.x, b.y);
        mma_f16(d + 8,  A1[0], A1[1], A1[2], A1[3], b.x, b.y);
        mma_f16(d + 4,  A0[0], A0[1], A0[2], A0[3], b.z, b.w);
        mma_f16(d + 12, A1[0], A1[1], A1[2], A1[3], b.z, b.w);
    }

    // ---- write out ----
    const int rlo = lane >> 2;
    const int o0  = 2 * (lane & 3);
#pragma unroll
    for (int mt = 0; mt < 2; mt++) {
#pragma unroll
        for (int nt = 0; nt < 2; nt++) {
            const float* dd = d + mt * 8 + nt * 4;
            int vlo = mt * 16 + rlo;
            int vhi = vlo + 8;
            int vox_lo = (bz + (w >> 1)) * HWs
                       + (by + (w & 1) * 4 + (vlo >> 3)) * 64 + bx + (vlo & 7);
            int vox_hi = (bz + (w >> 1)) * HWs
                       + (by + (w & 1) * 4 + (vhi >> 3)) * 64 + bx + (vhi & 7);
            out[(size_t)(nt * 8 + o0    ) * DHW + vox_lo] = dd[0];
            out[(size_t)(nt * 8 + o0 + 1) * DHW + vox_lo] = dd[1];
            out[(size_t)(nt * 8 + o0    ) * DHW + vox_hi] = dd[2];
            out[(size_t)(nt * 8 + o0 + 1) * DHW + vox_hi] = dd[3];
        }
    }
}

// ---------------------------------------------------------------------------
extern "C" void kernel_launch(void* const* d_in, const int* in_sizes, int n_in,
                              void* d_out, int out_size)
{
    const float* x    = (const float*)d_in[0];   // [16,64,64,64]
    const float* kern = (const float*)d_in[1];   // [27,16,16]
    const float* pk   = (const float*)d_in[2];   // [27,16,81]
    float* out = (float*)d_out;                  // [16,64,64,64]

    cudaFuncSetAttribute(k_gemm,   cudaFuncAttributeMaxDynamicSharedMemorySize, 56448);
    cudaFuncSetAttribute(k_deform, cudaFuncAttributeMaxDynamicSharedMemorySize, 70688);

    k_prep<<<1049, 256>>>(x, pk, kern);
    k_gemm<<<dim3(32, 64), 256, 56448>>>();
    k_deform<<<dim3(8, 8, 16), 256, 70688>>>(out);
}

// round 17
// speedup vs baseline: 1.0979x; 1.0353x over previous
#include <cuda_runtime.h>
#include <cuda_fp16.h>
#include <cstdint>

#define HWs  4096
#define DHW  262144

// ---------------- scratch (device globals; allocation-free rule) -----------
__device__ __half2 g_xth[(size_t)DHW * 8];    // x channel-last fp16 [v][c]
__device__ uint2   g_offh[(size_t)27 * DHW];  // offsets tap-major fp16 (oz,oy,ox,0)
__device__ uint4   g_BfragG[5184];            // gemm W frags [27][6][32] uint4
__device__ uint4   g_BfragD[864];             // einsum kern frags [27][32] uint4

// ---- helpers ----------------------------------------------------------------
__device__ __forceinline__ uint32_t smem_u32(const void* p) {
    uint32_t a;
    asm("{ .reg .u64 t; cvta.to.shared.u64 t, %1; cvt.u32.u64 %0, t; }" : "=r"(a) : "l"(p));
    return a;
}
__device__ __forceinline__ void cp_async16(uint32_t dst, const void* src) {
    asm volatile("cp.async.ca.shared.global [%0], [%1], 16;" :: "r"(dst), "l"(src) : "memory");
}
__device__ __forceinline__ void mma_f16(float* d, uint32_t a0, uint32_t a1,
                                        uint32_t a2, uint32_t a3,
                                        uint32_t b0, uint32_t b1) {
    asm volatile(
        "mma.sync.aligned.m16n8k16.row.col.f32.f16.f16.f32 "
        "{%0,%1,%2,%3}, {%4,%5,%6,%7}, {%8,%9}, {%0,%1,%2,%3};"
        : "+f"(d[0]), "+f"(d[1]), "+f"(d[2]), "+f"(d[3])
        : "r"(a0), "r"(a1), "r"(a2), "r"(a3), "r"(b0), "r"(b1));
}
#define LDM_X4(r, addr) asm volatile( \
    "ldmatrix.sync.aligned.m8n8.x4.shared.b16 {%0,%1,%2,%3}, [%4];" \
    : "=r"((r)[0]), "=r"((r)[1]), "=r"((r)[2]), "=r"((r)[3]) : "r"(addr))

// ---------------------------------------------------------------------------
// Kernel P: merged prep — blocks 0..1023 transpose x -> fp16 channel-last;
// blocks 1024..1044 build gemm W frags; blocks 1045..1048 build kern frags.
// ---------------------------------------------------------------------------
__global__ void __launch_bounds__(256) k_prep(const float* __restrict__ x,
                                              const float* __restrict__ pk,
                                              const float* __restrict__ kern)
{
    const int b = blockIdx.x;
    const int t = threadIdx.x;

    if (b < 1024) {
        int v = b * 256 + t;
        float vals[16];
#pragma unroll
        for (int c = 0; c < 16; c++)
            vals[c] = x[(size_t)c * DHW + v];
        __half2 h[8];
#pragma unroll
        for (int i = 0; i < 8; i++)
            h[i] = __floats2half2_rn(vals[2*i], vals[2*i+1]);
        uint4* dst = reinterpret_cast<uint4*>(g_xth + (size_t)v * 8);
        dst[0] = *reinterpret_cast<uint4*>(&h[0]);
        dst[1] = *reinterpret_cast<uint4*>(&h[4]);
    } else if (b < 1045) {
        int idx = (b - 1024) * 256 + t;
        if (idx >= 5184) return;
        int tap = idx / 192;
        int rem = idx - tap * 192;
        int np  = rem >> 5;
        int l   = rem & 31;
        int c0  = 2 * (l & 3);
        int n0  = 16 * np + (l >> 2);
        int n1  = n0 + 8;
        int kb  = tap * 16;
        float a0 = (n0 < 81) ? pk[(kb + c0    ) * 81 + n0] : 0.f;
        float a1 = (n0 < 81) ? pk[(kb + c0 + 1) * 81 + n0] : 0.f;
        float b0 = (n0 < 81) ? pk[(kb + c0 + 8) * 81 + n0] : 0.f;
        float b1 = (n0 < 81) ? pk[(kb + c0 + 9) * 81 + n0] : 0.f;
        float c2 = (n1 < 81) ? pk[(kb + c0    ) * 81 + n1] : 0.f;
        float c3 = (n1 < 81) ? pk[(kb + c0 + 1) * 81 + n1] : 0.f;
        float d2 = (n1 < 81) ? pk[(kb + c0 + 8) * 81 + n1] : 0.f;
        float d3 = (n1 < 81) ? pk[(kb + c0 + 9) * 81 + n1] : 0.f;
        __half2 h0 = __floats2half2_rn(a0, a1);
        __half2 h1 = __floats2half2_rn(b0, b1);
        __half2 h2 = __floats2half2_rn(c2, c3);
        __half2 h3 = __floats2half2_rn(d2, d3);
        g_BfragG[idx] = make_uint4(*reinterpret_cast<uint32_t*>(&h0),
                                   *reinterpret_cast<uint32_t*>(&h1),
                                   *reinterpret_cast<uint32_t*>(&h2),
                                   *reinterpret_cast<uint32_t*>(&h3));
    } else {
        int idx = (b - 1045) * 256 + t;
        if (idx >= 864) return;
        int tap = idx >> 5;
        int l   = idx & 31;
        int c0  = 2 * (l & 3);
        int o0  = l >> 2;
        int kb  = tap * 16;
        __half2 h0 = __floats2half2_rn(kern[(kb + c0    ) * 16 + o0],
                                       kern[(kb + c0 + 1) * 16 + o0]);
        __half2 h1 = __floats2half2_rn(kern[(kb + c0 + 8) * 16 + o0],
                                       kern[(kb + c0 + 9) * 16 + o0]);
        __half2 h2 = __floats2half2_rn(kern[(kb + c0    ) * 16 + o0 + 8],
                                       kern[(kb + c0 + 1) * 16 + o0 + 8]);
        __half2 h3 = __floats2half2_rn(kern[(kb + c0 + 8) * 16 + o0 + 8],
                                       kern[(kb + c0 + 9) * 16 + o0 + 8]);
        g_BfragD[idx] = make_uint4(*reinterpret_cast<uint32_t*>(&h0),
                                   *reinterpret_cast<uint32_t*>(&h1),
                                   *reinterpret_cast<uint32_t*>(&h2),
                                   *reinterpret_cast<uint32_t*>(&h3));
    }
}

// ---------------------------------------------------------------------------
// Kernel 1: offset GEMM. Triple-buffered B (one __syncthreads per group).
// SMEM: B 3 x 9216 @0; patch 38016 @27648. Total 65664. Stage reuses @0.
// ---------------------------------------------------------------------------
__global__ void __launch_bounds__(256, 3) k_gemm()
{
    extern __shared__ char smem[];
    const uint32_t smem_base = smem_u32(smem);
    uint4* bsm = reinterpret_cast<uint4*>(smem);               // 3 x 576 uint4
    uint32_t* patch = reinterpret_cast<uint32_t*>(smem + 27648);
    float* stage = reinterpret_cast<float*>(smem);

    const int t    = threadIdx.x;
    const int lane = t & 31;
    const int w    = t >> 5;
    const int mg    = w >> 1;
    const int nhalf = w & 1;
    const int z    = blockIdx.y;
    const int y0   = blockIdx.x * 2;

#pragma unroll
    for (int g = 0; g < 2; g++) {
        for (int i = t; i < 576; i += 256)
            cp_async16(smem_base + (uint32_t)((g * 576 + i) * 16),
                       g_BfragG + g * 576 + i);
        asm volatile("cp.async.commit_group;" ::: "memory");
    }

    const uint4* xthq = reinterpret_cast<const uint4*>(g_xth);
    for (int j = t; j < 1584; j += 256) {
        int q    = j & 1;
        int slot = j >> 1;
        int px = slot % 66;
        int qq = slot / 66;
        int py = qq & 3, pz = qq >> 2;
        int gz = z - 1 + pz, gy = y0 - 1 + py, gx = px - 1;
        uint4 v = make_uint4(0u, 0u, 0u, 0u);
        if ((unsigned)gz < 64u && (unsigned)gy < 64u && (unsigned)gx < 64u)
            v = xthq[(size_t)(gz * HWs + gy * 64 + gx) * 2 + q];
        *reinterpret_cast<uint4*>(patch + slot * 12 + q * 4) = v;
    }

    const int rowInTile = (lane & 7) + ((lane >> 3) & 1) * 8;
    const int khalf = lane >> 4;
    uint32_t abase[2];
#pragma unroll
    for (int mt = 0; mt < 2; mt++) {
        int r  = mg * 32 + mt * 16 + rowInTile;
        int sy = r >> 6, sx = r & 63;
        abase[mt] = smem_base + 27648u + (uint32_t)((sy * 66 + sx) * 48) + khalf * 16u;
    }

    float d[48];
#pragma unroll
    for (int i = 0; i < 48; i++) d[i] = 0.f;

    uint32_t rowoff = 0;
    int gm = 0;
    int b0buf = 0;     // g % 3
#pragma unroll 1
    for (int g = 0; g < 9; g++) {
        if (g < 8) { asm volatile("cp.async.wait_group 1;" ::: "memory"); }
        else       { asm volatile("cp.async.wait_group 0;" ::: "memory"); }
        __syncthreads();    // buffer g%3 visible to all; (g+2)%3 free (read in g-1)

        const uint4* bp = bsm + b0buf * 576 + nhalf * 96 + lane;
#pragma unroll
        for (int tl = 0; tl < 3; tl++) {
            const uint32_t aoff = rowoff + (uint32_t)(tl * 48);
            uint32_t A0[4], A1[4];
            LDM_X4(A0, abase[0] + aoff);
            LDM_X4(A1, abase[1] + aoff);
            const uint4* bpt = bp + tl * 192;
#pragma unroll
            for (int np = 0; np < 3; np++) {
                uint4 b = bpt[np * 32];
                float* d0 = d + (np * 4    ) * 4;
                float* d1 = d + (np * 4 + 1) * 4;
                float* d2 = d + (np * 4 + 2) * 4;
                float* d3 = d + (np * 4 + 3) * 4;
                mma_f16(d0, A0[0], A0[1], A0[2], A0[3], b.x, b.y);
                mma_f16(d1, A1[0], A1[1], A1[2], A1[3], b.x, b.y);
                mma_f16(d2, A0[0], A0[1], A0[2], A0[3], b.z, b.w);
                mma_f16(d3, A1[0], A1[1], A1[2], A1[3], b.z, b.w);
            }
        }

        if (g + 2 < 9) {
            int dst = (g + 2) % 3;
            for (int i = t; i < 576; i += 256)
                cp_async16(smem_base + (uint32_t)((dst * 576 + i) * 16),
                           g_BfragG + (g + 2) * 576 + i);
        }
        asm volatile("cp.async.commit_group;" ::: "memory");

        rowoff += (uint32_t)(66 * 48);
        if (++gm == 3) { gm = 0; rowoff += (uint32_t)(66 * 48); }
        if (++b0buf == 3) b0buf = 0;
    }
    asm volatile("cp.async.wait_group 0;" ::: "memory");
    __syncthreads();   // B + patch dead; reuse as stage

    const int rlo  = lane >> 2;
    const int col0 = 2 * (lane & 3);
#pragma unroll
    for (int mt = 0; mt < 2; mt++) {
#pragma unroll
        for (int np = 0; np < 3; np++) {
#pragma unroll
            for (int ntl = 0; ntl < 2; ntl++) {
                const float* dd = d + ((np * 2 + ntl) * 2 + mt) * 4;
                int lr0 = mg * 32 + mt * 16 + rlo;
                int col = (2 * (nhalf * 3 + np) + ntl) * 8 + col0;
                stage[lr0 * 100 + col    ] = dd[0];
                stage[lr0 * 100 + col + 1] = dd[1];
                stage[(lr0 + 8) * 100 + col    ] = dd[2];
                stage[(lr0 + 8) * 100 + col + 1] = dd[3];
            }
        }
    }
    __syncthreads();

    for (int i = t; i < 3456; i += 256) {
        int tap = i >> 7;
        int v   = i & 127;
        int vox = z * HWs + (y0 + (v >> 6)) * 64 + (v & 63);
        const float* s = stage + v * 100 + 3 * tap;
        __half2 h0 = __floats2half2_rn(s[0], s[1]);
        __half2 h1 = __floats2half2_rn(s[2], 0.f);
        g_offh[(size_t)tap * DHW + vox] =
            make_uint2(*reinterpret_cast<uint32_t*>(&h0),
                       *reinterpret_cast<uint32_t*>(&h1));
    }
}

// ---------------------------------------------------------------------------
// Kernel 2: deformable gather + HMMA einsum. 256 thr / 8 warps, 4x8x8 tile,
// 3 blocks/SM. Region shrunk to [8][12][12] (exact coverage for |off|<1;
// larger offsets use the exact fallback). A-stage double-buffered: one
// syncwarp per tap (RAW only).
// SMEM: region 2 planes x 1152 pts x 16 B @0 (36864 B); kern frags 13824 B
// @36864; A stage 8 warps x 2048 B @50688. Total 67072 B.
// ---------------------------------------------------------------------------
__global__ void __launch_bounds__(256, 3) k_deform(float* __restrict__ out)
{
    extern __shared__ char smem[];
    const uint4* xrq = reinterpret_cast<const uint4*>(smem);   // 2 x 1152 uint4
    const uint4* bfr = reinterpret_cast<const uint4*>(smem + 36864);
    const uint32_t smem_base = smem_u32(smem);

    const int t    = threadIdx.x;
    const int lane = t & 31;
    const int w    = t >> 5;

    {
        uint4* bd = reinterpret_cast<uint4*>(smem + 36864);
        for (int i = t; i < 864; i += 256) bd[i] = g_BfragD[i];
    }

    const int bz = blockIdx.z * 4, by = blockIdx.y * 8, bx = blockIdx.x * 8;
    const int roz = bz - 2, roy = by - 2, rox = bx - 2;

    // region: 1152 points ([8][12][12]) x 2 planes, 16 B each
    {
        const uint4* xthq = reinterpret_cast<const uint4*>(g_xth);
        uint4* xw = reinterpret_cast<uint4*>(smem);
        for (int u = t; u < 2304; u += 256) {
            int q = u & 1;
            int p = u >> 1;
            int rx = p % 12;
            int p2 = p / 12;
            int ry = p2 % 12;
            int rz = p2 / 12;
            int gz = roz + rz, gy = roy + ry, gx = rox + rx;
            uint4 v = make_uint4(0u, 0u, 0u, 0u);
            if ((unsigned)gz < 64u && (unsigned)gy < 64u && (unsigned)gx < 64u)
                v = xthq[(size_t)(gz * HWs + gy * 64 + gx) * 2 + q];
            xw[q * 1152 + p] = v;
        }
    }
    __syncthreads();

    const int lx = t & 7, ly = (t >> 3) & 7, lz = t >> 6;   // lz 0..3
    const int pz = bz + lz, py = by + ly, px = bx + lx;
    const int vox = pz * HWs + py * 64 + px;
    const uint2* offp = g_offh + vox;

    // A-stage: per-warp 2 x 1024 B, layout [buf][mt][khalf][row*16]
    const uint32_t asb = 50688u + (uint32_t)w * 2048u;
    const uint32_t stoff = asb + ((uint32_t)(lane >> 4)) * 512u
                         + (uint32_t)(lane & 15) * 16u;
    const uint32_t adr0  = smem_base + asb + (uint32_t)(lane & 15) * 16u
                         + (uint32_t)(lane >> 4) * 256u;

    float d[16];
#pragma unroll
    for (int q = 0; q < 16; q++) d[q] = 0.f;

    int kd = 0, kh = 0, kw = 0;
#pragma unroll 1
    for (int k = 0; k < 27; k++) {
        uint2 ob = offp[(size_t)k * DHW];
        float2 ozy = __half22float2(*reinterpret_cast<__half2*>(&ob.x));
        float2 oxp = __half22float2(*reinterpret_cast<__half2*>(&ob.y));
        float cz = (float)(pz + kd - 1) + ozy.x;
        float cy = (float)(py + kh - 1) + ozy.y;
        float cx = (float)(px + kw - 1) + oxp.x;
        if (++kw == 3) { kw = 0; if (++kh == 3) { kh = 0; ++kd; } }

        float z0f = floorf(cz), y0f = floorf(cy), x0f = floorf(cx);
        float fz = cz - z0f, fy = cy - y0f, fx = cx - x0f;
        int z0 = (int)z0f, y0 = (int)y0f, x0 = (int)x0f;
        int lz0 = z0 - roz, ly0 = y0 - roy, lx0 = x0 - rox;

        const __half2 wx0h = __float2half2_rn(1.f - fx);
        const __half2 wx1h = __float2half2_rn(fx);

        __half2 ah[8];
#pragma unroll
        for (int j = 0; j < 8; j++) ah[j] = __float2half2_rn(0.f);

        if ((unsigned)lz0 <= 6u && (unsigned)ly0 <= 10u && (unsigned)lx0 <= 10u) {
            // fast path: batch one z-slab's 8 loads, then consume (MLP 8)
#pragma unroll
            for (int dz = 0; dz < 2; dz++) {
                float wz = dz ? fz : 1.f - fz;
                const int ptb = (lz0 + dz) * 144 + ly0 * 12 + lx0;
                uint4 p0a = xrq[ptb];             uint4 q0a = xrq[ptb + 1];
                uint4 p1a = xrq[1152 + ptb];      uint4 q1a = xrq[1152 + ptb + 1];
                uint4 p0b = xrq[ptb + 12];        uint4 q0b = xrq[ptb + 13];
                uint4 p1b = xrq[1152 + ptb + 12]; uint4 q1b = xrq[1152 + ptb + 13];
                __half2 wa = __float2half2_rn(wz * (1.f - fy));
                __half2 wb = __float2half2_rn(wz * fy);
#pragma unroll
                for (int j = 0; j < 4; j++) {
                    __half2 ta = __hfma2(*(reinterpret_cast<__half2*>(&q0a) + j), wx1h,
                                 __hmul2(*(reinterpret_cast<__half2*>(&p0a) + j), wx0h));
                    ah[j] = __hfma2(ta, wa, ah[j]);
                    __half2 ua = __hfma2(*(reinterpret_cast<__half2*>(&q1a) + j), wx1h,
                                 __hmul2(*(reinterpret_cast<__half2*>(&p1a) + j), wx0h));
                    ah[j + 4] = __hfma2(ua, wa, ah[j + 4]);
                    __half2 tb = __hfma2(*(reinterpret_cast<__half2*>(&q0b) + j), wx1h,
                                 __hmul2(*(reinterpret_cast<__half2*>(&p0b) + j), wx0h));
                    ah[j] = __hfma2(tb, wb, ah[j]);
                    __half2 ub = __hfma2(*(reinterpret_cast<__half2*>(&q1b) + j), wx1h,
                                 __hmul2(*(reinterpret_cast<__half2*>(&p1b) + j), wx0h));
                    ah[j + 4] = __hfma2(ub, wb, ah[j + 4]);
                }
            }
        } else {
            // exact fallback: per-corner validity, global fp16 reads
#pragma unroll
            for (int dz = 0; dz < 2; dz++) {
                float wz = dz ? fz : 1.f - fz;
#pragma unroll
                for (int dy = 0; dy < 2; dy++) {
                    __half2 wzyh = __float2half2_rn(wz * (dy ? fy : 1.f - fy));
                    int zi = z0 + dz, yi = y0 + dy;
                    bool okzy = ((unsigned)zi < 64u) && ((unsigned)yi < 64u);
                    uint4 p0 = make_uint4(0,0,0,0), p1 = p0, q0 = p0, q1 = p0;
                    if (okzy && (unsigned)x0 < 64u) {
                        const uint4* g = reinterpret_cast<const uint4*>(
                            g_xth + (size_t)(zi * HWs + yi * 64 + x0) * 8);
                        p0 = g[0]; p1 = g[1];
                    }
                    if (okzy && (unsigned)(x0 + 1) < 64u) {
                        const uint4* g = reinterpret_cast<const uint4*>(
                            g_xth + (size_t)(zi * HWs + yi * 64 + x0 + 1) * 8);
                        q0 = g[0]; q1 = g[1];
                    }
#pragma unroll
                    for (int j = 0; j < 4; j++) {
                        __half2 pj = *(reinterpret_cast<__half2*>(&p0) + j);
                        __half2 qj = *(reinterpret_cast<__half2*>(&q0) + j);
                        __half2 tj = __hfma2(qj, wx1h, __hmul2(pj, wx0h));
                        ah[j] = __hfma2(tj, wzyh, ah[j]);
                        __half2 pk2 = *(reinterpret_cast<__half2*>(&p1) + j);
                        __half2 qk2 = *(reinterpret_cast<__half2*>(&q1) + j);
                        __half2 uk = __hfma2(qk2, wx1h, __hmul2(pk2, wx0h));
                        ah[j + 4] = __hfma2(uk, wzyh, ah[j + 4]);
                    }
                }
            }
        }

        // ---- einsum via HMMA: stage ah (double-buffered) -> ldmatrix -> mma
        const uint32_t bufo = (uint32_t)(k & 1) * 1024u;
        uint4* s0 = reinterpret_cast<uint4*>(smem + stoff + bufo);
        s0[0]  = *reinterpret_cast<uint4*>(&ah[0]);
        s0[16] = *reinterpret_cast<uint4*>(&ah[4]);   // khalf1 @ +256 B
        __syncwarp();                                 // RAW only
        uint32_t A0[4], A1[4];
        LDM_X4(A0, adr0 + bufo);
        LDM_X4(A1, adr0 + bufo + 512u);
        uint4 b = bfr[k * 32 + lane];
        mma_f16(d,      A0[0], A0[1], A0[2], A0[3], b.x, b.y);
        mma_f16(d + 8,  A1[0], A1[1], A1[2], A1[3], b.x, b.y);
        mma_f16(d + 4,  A0[0], A0[1], A0[2], A0[3], b.z, b.w);
        mma_f16(d + 12, A1[0], A1[1], A1[2], A1[3], b.z, b.w);
    }

    // ---- write out ----
    const int rlo = lane >> 2;
    const int o0  = 2 * (lane & 3);
#pragma unroll
    for (int mt = 0; mt < 2; mt++) {
#pragma unroll
        for (int nt = 0; nt < 2; nt++) {
            const float* dd = d + mt * 8 + nt * 4;
            int vlo = mt * 16 + rlo;
            int vhi = vlo + 8;
            int vox_lo = (bz + (w >> 1)) * HWs
                       + (by + (w & 1) * 4 + (vlo >> 3)) * 64 + bx + (vlo & 7);
            int vox_hi = (bz + (w >> 1)) * HWs
                       + (by + (w & 1) * 4 + (vhi >> 3)) * 64 + bx + (vhi & 7);
            out[(size_t)(nt * 8 + o0    ) * DHW + vox_lo] = dd[0];
            out[(size_t)(nt * 8 + o0 + 1) * DHW + vox_lo] = dd[1];
            out[(size_t)(nt * 8 + o0    ) * DHW + vox_hi] = dd[2];
            out[(size_t)(nt * 8 + o0 + 1) * DHW + vox_hi] = dd[3];
        }
    }
}

// ---------------------------------------------------------------------------
extern "C" void kernel_launch(void* const* d_in, const int* in_sizes, int n_in,
                              void* d_out, int out_size)
{
    const float* x    = (const float*)d_in[0];   // [16,64,64,64]
    const float* kern = (const float*)d_in[1];   // [27,16,16]
    const float* pk   = (const float*)d_in[2];   // [27,16,81]
    float* out = (float*)d_out;                  // [16,64,64,64]

    cudaFuncSetAttribute(k_gemm,   cudaFuncAttributeMaxDynamicSharedMemorySize, 65664);
    cudaFuncSetAttribute(k_deform, cudaFuncAttributeMaxDynamicSharedMemorySize, 67072);

    k_prep<<<1049, 256>>>(x, pk, kern);
    k_gemm<<<dim3(32, 64), 256, 65664>>>();
    k_deform<<<dim3(8, 8, 16), 256, 67072>>>(out);
}